// round 1
// baseline (speedup 1.0000x reference)
#include <cuda_runtime.h>

#define NN   10000
#define EE   640000
#define KDIM 128

// ---------------- scratch (device globals, no allocation) ----------------
__device__ int   g_cnt[NN];
__device__ int   g_rowptr[NN + 1];
__device__ int   g_cursor[NN];
__device__ int   g_esrc[EE];
__device__ float g_z[NN * KDIM];
__device__ float g_h[NN * KDIM];

// ---------------- CSR build ----------------
__global__ void zero_cnt_kernel() {
    int i = blockIdx.x * blockDim.x + threadIdx.x;
    if (i < NN) g_cnt[i] = 0;
}

__global__ void hist_kernel(const int* __restrict__ dst) {
    int e = blockIdx.x * blockDim.x + threadIdx.x;
    if (e < EE) atomicAdd(&g_cnt[dst[e]], 1);
}

// one block, 1024 threads, 10 elements each -> exclusive scan of counts
__global__ void scan_kernel() {
    __shared__ int part[1024];
    const int CH = 10;
    int t = threadIdx.x;
    int loc[CH];
    int s = 0;
    int base = t * CH;
#pragma unroll
    for (int i = 0; i < CH; i++) {
        int idx = base + i;
        int c = (idx < NN) ? g_cnt[idx] : 0;
        loc[i] = s;
        s += c;
    }
    part[t] = s;
    __syncthreads();
    for (int off = 1; off < 1024; off <<= 1) {
        int v = (t >= off) ? part[t - off] : 0;
        __syncthreads();
        part[t] += v;
        __syncthreads();
    }
    int excl = part[t] - s;  // exclusive prefix of this thread's chunk
#pragma unroll
    for (int i = 0; i < CH; i++) {
        int idx = base + i;
        if (idx < NN) {
            int v = excl + loc[i];
            g_rowptr[idx] = v;
            g_cursor[idx] = v;
        }
    }
    if (t == 1023) g_rowptr[NN] = part[1023];
}

__global__ void scatter_kernel(const int* __restrict__ src, const int* __restrict__ dst) {
    int e = blockIdx.x * blockDim.x + threadIdx.x;
    if (e < EE) {
        int d = dst[e];
        int p = atomicAdd(&g_cursor[d], 1);
        g_esrc[p] = src[e];
    }
}

// ---------------- SGEMM: C[M,Nc] = A[M,128] @ B[128,Nc] ----------------
// BM=64, BN=64, BK=32, 256 threads, 4x4 microtile.
__global__ void gemm64_kernel(const float* __restrict__ A, const float* __restrict__ B,
                              float* __restrict__ C, int M, int Nc) {
    __shared__ float As[32][68];   // [k][m], pad 68 keeps float4 reads 16B aligned
    __shared__ float Bs[32][64];   // [k][n]

    int tid = threadIdx.x;
    int bm = blockIdx.x * 64;
    int bn = blockIdx.y * 64;
    int tx = tid & 15;
    int ty = tid >> 4;

    float acc[4][4] = {};

    for (int k0 = 0; k0 < KDIM; k0 += 32) {
        // load A tile 64x32 (coalesced along k)
#pragma unroll
        for (int i = 0; i < 8; i++) {
            int e = tid + i * 256;       // 0..2047
            int k = e & 31;
            int m = e >> 5;
            int row = bm + m;
            As[k][m] = (row < M) ? A[row * KDIM + k0 + k] : 0.f;
        }
        // load B tile 32x64 (coalesced along n)
#pragma unroll
        for (int i = 0; i < 8; i++) {
            int e = tid + i * 256;
            int n = e & 63;
            int k = e >> 6;
            Bs[k][n] = B[(k0 + k) * Nc + bn + n];
        }
        __syncthreads();
#pragma unroll
        for (int k = 0; k < 32; k++) {
            float4 a = *(const float4*)&As[k][ty * 4];
            float4 b = *(const float4*)&Bs[k][tx * 4];
            float av[4] = {a.x, a.y, a.z, a.w};
            float bv[4] = {b.x, b.y, b.z, b.w};
#pragma unroll
            for (int i = 0; i < 4; i++)
#pragma unroll
                for (int j = 0; j < 4; j++)
                    acc[i][j] += av[i] * bv[j];
        }
        __syncthreads();
    }
#pragma unroll
    for (int i = 0; i < 4; i++) {
        int row = bm + ty * 4 + i;
        if (row < M) {
            float4 r = make_float4(acc[i][0], acc[i][1], acc[i][2], acc[i][3]);
            *(float4*)&C[row * Nc + bn + tx * 4] = r;
        }
    }
}

// ---------------- aggregation: out[v] = z[v] + sum_{u in row v} z[u] ----------------
// warp per row, 128 cols: each lane owns one float4; 4 independent accumulators for MLP.
__global__ void agg128_kernel(const float* __restrict__ z, float* __restrict__ out) {
    int gw = (blockIdx.x * blockDim.x + threadIdx.x) >> 5;
    if (gw >= NN) return;
    int lane = threadIdx.x & 31;
    const float4* z4 = (const float4*)z;

    float4 a0 = z4[gw * 32 + lane];
    float4 a1 = make_float4(0, 0, 0, 0);
    float4 a2 = make_float4(0, 0, 0, 0);
    float4 a3 = make_float4(0, 0, 0, 0);

    int s = g_rowptr[gw], e = g_rowptr[gw + 1];
    int j = s;
    for (; j + 4 <= e; j += 4) {
        int u0 = g_esrc[j], u1 = g_esrc[j + 1], u2 = g_esrc[j + 2], u3 = g_esrc[j + 3];
        float4 v0 = z4[u0 * 32 + lane];
        float4 v1 = z4[u1 * 32 + lane];
        float4 v2 = z4[u2 * 32 + lane];
        float4 v3 = z4[u3 * 32 + lane];
        a0.x += v0.x; a0.y += v0.y; a0.z += v0.z; a0.w += v0.w;
        a1.x += v1.x; a1.y += v1.y; a1.z += v1.z; a1.w += v1.w;
        a2.x += v2.x; a2.y += v2.y; a2.z += v2.z; a2.w += v2.w;
        a3.x += v3.x; a3.y += v3.y; a3.z += v3.z; a3.w += v3.w;
    }
    for (; j < e; j++) {
        float4 v = z4[g_esrc[j] * 32 + lane];
        a0.x += v.x; a0.y += v.y; a0.z += v.z; a0.w += v.w;
    }
    float4 r;
    r.x = (a0.x + a1.x) + (a2.x + a3.x);
    r.y = (a0.y + a1.y) + (a2.y + a3.y);
    r.z = (a0.z + a1.z) + (a2.z + a3.z);
    r.w = (a0.w + a1.w) + (a2.w + a3.w);
    ((float4*)out)[gw * 32 + lane] = r;
}

// 64-col version (last layer), each lane owns one float2
__global__ void agg64_kernel(const float* __restrict__ z, float* __restrict__ out) {
    int gw = (blockIdx.x * blockDim.x + threadIdx.x) >> 5;
    if (gw >= NN) return;
    int lane = threadIdx.x & 31;
    const float2* z2 = (const float2*)z;

    float2 a0 = z2[gw * 32 + lane];
    float2 a1 = make_float2(0, 0);
    float2 a2 = make_float2(0, 0);
    float2 a3 = make_float2(0, 0);

    int s = g_rowptr[gw], e = g_rowptr[gw + 1];
    int j = s;
    for (; j + 4 <= e; j += 4) {
        int u0 = g_esrc[j], u1 = g_esrc[j + 1], u2 = g_esrc[j + 2], u3 = g_esrc[j + 3];
        float2 v0 = z2[u0 * 32 + lane];
        float2 v1 = z2[u1 * 32 + lane];
        float2 v2 = z2[u2 * 32 + lane];
        float2 v3 = z2[u3 * 32 + lane];
        a0.x += v0.x; a0.y += v0.y;
        a1.x += v1.x; a1.y += v1.y;
        a2.x += v2.x; a2.y += v2.y;
        a3.x += v3.x; a3.y += v3.y;
    }
    for (; j < e; j++) {
        float2 v = z2[g_esrc[j] * 32 + lane];
        a0.x += v.x; a0.y += v.y;
    }
    float2 r;
    r.x = (a0.x + a1.x) + (a2.x + a3.x);
    r.y = (a0.y + a1.y) + (a2.y + a3.y);
    ((float2*)out)[gw * 32 + lane] = r;
}

// ---------------- launch ----------------
extern "C" void kernel_launch(void* const* d_in, const int* in_sizes, int n_in,
                              void* d_out, int out_size) {
    const float* feat = (const float*)d_in[0];
    const float* W0   = (const float*)d_in[1];
    const float* W1   = (const float*)d_in[2];
    const float* W2   = (const float*)d_in[3];
    const int*   src  = (const int*)d_in[4];
    const int*   dst  = (const int*)d_in[5];
    float*       out  = (float*)d_out;

    void *pz, *ph;
    cudaGetSymbolAddress(&pz, g_z);
    cudaGetSymbolAddress(&ph, g_h);
    float* z = (float*)pz;
    float* h = (float*)ph;

    // build CSR (dst-sorted edges) once per launch
    zero_cnt_kernel<<<(NN + 255) / 256, 256>>>();
    hist_kernel<<<EE / 256, 256>>>(dst);
    scan_kernel<<<1, 1024>>>();
    scatter_kernel<<<EE / 256, 256>>>(src, dst);

    dim3 g2((NN + 63) / 64, 2);
    dim3 g1((NN + 63) / 64, 1);
    const int AGG_BLOCKS = (NN * 32 + 255) / 256;

    // layer 0: z = feat @ W0 ; h = z + agg(z)
    gemm64_kernel<<<g2, 256>>>(feat, W0, z, NN, 128);
    agg128_kernel<<<AGG_BLOCKS, 256>>>(z, h);
    // layer 1
    gemm64_kernel<<<g2, 256>>>(h, W1, z, NN, 128);
    agg128_kernel<<<AGG_BLOCKS, 256>>>(z, h);
    // layer 2 (64 cols)
    gemm64_kernel<<<g1, 256>>>(h, W2, z, NN, 64);
    agg64_kernel<<<AGG_BLOCKS, 256>>>(z, out);
}

// round 4
// speedup vs baseline: 1.2612x; 1.2612x over previous
#include <cuda_runtime.h>
#include <cuda_fp16.h>

#define NN   10000
#define EE   640000
#define KDIM 128
#define CAP  160

// ---------------- scratch (device globals, no allocation) ----------------
__device__ int    g_cnt[NN];
__device__ int    g_eb[NN * CAP];          // padded per-node src buckets
__device__ float  g_z[NN * KDIM];
__device__ float  g_h[NN * KDIM];
__device__ __half g_zh[NN * KDIM];         // fp16 copy of z for gathers

// ---------------- CSR build (bucketed, single pass) ----------------
__global__ void zero_cnt_kernel() {
    int i = blockIdx.x * blockDim.x + threadIdx.x;
    if (i < NN) g_cnt[i] = 0;
}

__global__ void scatter_kernel(const int* __restrict__ src, const int* __restrict__ dst) {
    int t = blockIdx.x * blockDim.x + threadIdx.x;   // one thread = 4 edges
    if (t * 4 >= EE) return;
    int4 dv = ((const int4*)dst)[t];
    int4 sv = ((const int4*)src)[t];
    int p0 = atomicAdd(&g_cnt[dv.x], 1);
    int p1 = atomicAdd(&g_cnt[dv.y], 1);
    int p2 = atomicAdd(&g_cnt[dv.z], 1);
    int p3 = atomicAdd(&g_cnt[dv.w], 1);
    g_eb[dv.x * CAP + p0] = sv.x;
    g_eb[dv.y * CAP + p1] = sv.y;
    g_eb[dv.z * CAP + p2] = sv.z;
    g_eb[dv.w * CAP + p3] = sv.w;
}

// ---------------- SGEMM: C[M,Nc] = A[M,128] @ B[128,Nc], + half copy ----------------
__global__ void gemm64_kernel(const float* __restrict__ A, const float* __restrict__ B,
                              float* __restrict__ C, __half* __restrict__ Ch,
                              int M, int Nc) {
    __shared__ float As[32][68];   // [k][m], pad keeps float4 reads 16B aligned
    __shared__ float Bs[32][64];   // [k][n]

    int tid = threadIdx.x;
    int bm = blockIdx.x * 64;
    int bn = blockIdx.y * 64;
    int tx = tid & 15;
    int ty = tid >> 4;

    float acc[4][4] = {};

    for (int k0 = 0; k0 < KDIM; k0 += 32) {
#pragma unroll
        for (int i = 0; i < 8; i++) {
            int e = tid + i * 256;
            int k = e & 31;
            int m = e >> 5;
            int row = bm + m;
            As[k][m] = (row < M) ? A[row * KDIM + k0 + k] : 0.f;
        }
#pragma unroll
        for (int i = 0; i < 8; i++) {
            int e = tid + i * 256;
            int n = e & 63;
            int k = e >> 6;
            Bs[k][n] = B[(k0 + k) * Nc + bn + n];
        }
        __syncthreads();
#pragma unroll
        for (int k = 0; k < 32; k++) {
            float4 a = *(const float4*)&As[k][ty * 4];
            float4 b = *(const float4*)&Bs[k][tx * 4];
            float av[4] = {a.x, a.y, a.z, a.w};
            float bv[4] = {b.x, b.y, b.z, b.w};
#pragma unroll
            for (int i = 0; i < 4; i++)
#pragma unroll
                for (int j = 0; j < 4; j++)
                    acc[i][j] += av[i] * bv[j];
        }
        __syncthreads();
    }
#pragma unroll
    for (int i = 0; i < 4; i++) {
        int row = bm + ty * 4 + i;
        if (row < M) {
            float4 r = make_float4(acc[i][0], acc[i][1], acc[i][2], acc[i][3]);
            *(float4*)&C[row * Nc + bn + tx * 4] = r;
            __half2 p0 = __floats2half2_rn(acc[i][0], acc[i][1]);
            __half2 p1 = __floats2half2_rn(acc[i][2], acc[i][3]);
            uint2 hp;
            hp.x = *(unsigned*)&p0;
            hp.y = *(unsigned*)&p1;
            *(uint2*)&Ch[row * Nc + bn + tx * 4] = hp;
        }
    }
}

// ---------------- aggregation: out[v] = z[v] + sum_{u in bucket v} z[u] ----------------
__device__ __forceinline__ float4 h4_to_f4(uint2 r) {
    __half2 h0 = *(__half2*)&r.x;
    __half2 h1 = *(__half2*)&r.y;
    float2 f0 = __half22float2(h0);
    float2 f1 = __half22float2(h1);
    return make_float4(f0.x, f0.y, f1.x, f1.y);
}

// 128 cols: warp per row, lane owns 4 cols (8B fp16 loads), 4-edge unroll for MLP
__global__ void agg128_kernel(const float* __restrict__ z, const __half* __restrict__ zh,
                              float* __restrict__ out) {
    int gw = (blockIdx.x * blockDim.x + threadIdx.x) >> 5;
    if (gw >= NN) return;
    int lane = threadIdx.x & 31;
    const float4* z4 = (const float4*)z;
    const uint2* zh2 = (const uint2*)zh;

    float4 self = z4[gw * 32 + lane];
    float4 a0 = make_float4(0, 0, 0, 0);
    float4 a1 = make_float4(0, 0, 0, 0);
    float4 a2 = make_float4(0, 0, 0, 0);
    float4 a3 = make_float4(0, 0, 0, 0);

    int n = g_cnt[gw];
    int s = gw * CAP;
    int j = 0;
    for (; j + 4 <= n; j += 4) {
        int u0 = g_eb[s + j], u1 = g_eb[s + j + 1], u2 = g_eb[s + j + 2], u3 = g_eb[s + j + 3];
        float4 v0 = h4_to_f4(zh2[u0 * 32 + lane]);
        float4 v1 = h4_to_f4(zh2[u1 * 32 + lane]);
        float4 v2 = h4_to_f4(zh2[u2 * 32 + lane]);
        float4 v3 = h4_to_f4(zh2[u3 * 32 + lane]);
        a0.x += v0.x; a0.y += v0.y; a0.z += v0.z; a0.w += v0.w;
        a1.x += v1.x; a1.y += v1.y; a1.z += v1.z; a1.w += v1.w;
        a2.x += v2.x; a2.y += v2.y; a2.z += v2.z; a2.w += v2.w;
        a3.x += v3.x; a3.y += v3.y; a3.z += v3.z; a3.w += v3.w;
    }
    for (; j < n; j++) {
        float4 v = h4_to_f4(zh2[g_eb[s + j] * 32 + lane]);
        a0.x += v.x; a0.y += v.y; a0.z += v.z; a0.w += v.w;
    }
    float4 r;
    r.x = self.x + (a0.x + a1.x) + (a2.x + a3.x);
    r.y = self.y + (a0.y + a1.y) + (a2.y + a3.y);
    r.z = self.z + (a0.z + a1.z) + (a2.z + a3.z);
    r.w = self.w + (a0.w + a1.w) + (a2.w + a3.w);
    ((float4*)out)[gw * 32 + lane] = r;
}

// 64 cols: lane owns 2 cols (4B fp16 loads)
__global__ void agg64_kernel(const float* __restrict__ z, const __half* __restrict__ zh,
                             float* __restrict__ out) {
    int gw = (blockIdx.x * blockDim.x + threadIdx.x) >> 5;
    if (gw >= NN) return;
    int lane = threadIdx.x & 31;
    const float2* z2 = (const float2*)z;
    const __half2* zhh = (const __half2*)zh;

    float2 self = z2[gw * 32 + lane];
    float2 a0 = make_float2(0, 0);
    float2 a1 = make_float2(0, 0);
    float2 a2 = make_float2(0, 0);
    float2 a3 = make_float2(0, 0);

    int n = g_cnt[gw];
    int s = gw * CAP;
    int j = 0;
    for (; j + 4 <= n; j += 4) {
        int u0 = g_eb[s + j], u1 = g_eb[s + j + 1], u2 = g_eb[s + j + 2], u3 = g_eb[s + j + 3];
        float2 v0 = __half22float2(zhh[u0 * 32 + lane]);
        float2 v1 = __half22float2(zhh[u1 * 32 + lane]);
        float2 v2 = __half22float2(zhh[u2 * 32 + lane]);
        float2 v3 = __half22float2(zhh[u3 * 32 + lane]);
        a0.x += v0.x; a0.y += v0.y;
        a1.x += v1.x; a1.y += v1.y;
        a2.x += v2.x; a2.y += v2.y;
        a3.x += v3.x; a3.y += v3.y;
    }
    for (; j < n; j++) {
        float2 v = __half22float2(zhh[g_eb[s + j] * 32 + lane]);
        a0.x += v.x; a0.y += v.y;
    }
    float2 r;
    r.x = self.x + (a0.x + a1.x) + (a2.x + a3.x);
    r.y = self.y + (a0.y + a1.y) + (a2.y + a3.y);
    ((float2*)out)[gw * 32 + lane] = r;
}

// ---------------- launch ----------------
extern "C" void kernel_launch(void* const* d_in, const int* in_sizes, int n_in,
                              void* d_out, int out_size) {
    const float* feat = (const float*)d_in[0];
    const float* W0   = (const float*)d_in[1];
    const float* W1   = (const float*)d_in[2];
    const float* W2   = (const float*)d_in[3];
    const int*   src  = (const int*)d_in[4];
    const int*   dst  = (const int*)d_in[5];
    float*       out  = (float*)d_out;

    void *pz, *ph, *pzh;
    cudaGetSymbolAddress(&pz, g_z);
    cudaGetSymbolAddress(&ph, g_h);
    cudaGetSymbolAddress(&pzh, g_zh);
    float*  z  = (float*)pz;
    float*  h  = (float*)ph;
    __half* zh = (__half*)pzh;

    // CSR build: zero + single-pass bucketed scatter
    zero_cnt_kernel<<<(NN + 255) / 256, 256>>>();
    scatter_kernel<<<(EE / 4 + 255) / 256, 256>>>(src, dst);

    dim3 g2((NN + 63) / 64, 2);
    dim3 g1((NN + 63) / 64, 1);
    const int AGG_BLOCKS = (NN * 32 + 255) / 256;

    // layer 0: z = feat @ W0 ; h = z + agg(z)
    gemm64_kernel<<<g2, 256>>>(feat, W0, z, zh, NN, 128);
    agg128_kernel<<<AGG_BLOCKS, 256>>>(z, zh, h);
    // layer 1
    gemm64_kernel<<<g2, 256>>>(h, W1, z, zh, NN, 128);
    agg128_kernel<<<AGG_BLOCKS, 256>>>(z, zh, h);
    // layer 2 (64 cols)
    gemm64_kernel<<<g1, 256>>>(h, W2, z, zh, NN, 64);
    agg64_kernel<<<AGG_BLOCKS, 256>>>(z, zh, out);
}

// round 7
// speedup vs baseline: 1.6322x; 1.2941x over previous
#include <cuda_runtime.h>
#include <cuda_fp16.h>

#define NN   10000
#define EE   640000
#define KDIM 128
#define CAP  160

// gemm0 tiling: (10000+63)/64 = 157 row-blocks, 2 col-blocks of 64 over Nc=128
#define GEMM0_BLOCKS 314
#define SCAT_BLOCKS  625            // 625*256*4 = 640000 edges
#define FUSED_BLOCKS (GEMM0_BLOCKS + SCAT_BLOCKS)

// ---------------- scratch (device globals, no allocation) ----------------
__device__ int    g_cnt[NN];
__device__ int    g_eb[NN * CAP];          // padded per-node src buckets
__device__ float  g_z[NN * KDIM];
__device__ float  g_h[NN * KDIM];
__device__ __half g_zh[NN * KDIM];         // fp16 copy of z for gathers

__device__ __forceinline__ __half2 u2h(unsigned u) { return *reinterpret_cast<__half2*>(&u); }

// ---------------- zero counters ----------------
__global__ void zero_cnt_kernel() {
    int i = blockIdx.x * blockDim.x + threadIdx.x;
    if (i < NN) g_cnt[i] = 0;
}

// ---------------- SGEMM body: C[M,Nc] = A[M,128] @ B[128,Nc], + half copy ----------------
__device__ __forceinline__ void gemm_body(const float* __restrict__ A, const float* __restrict__ B,
                                          float* __restrict__ C, __half* __restrict__ Ch,
                                          int M, int Nc, int bm, int bn) {
    __shared__ float As[32][68];   // [k][m], pad keeps float4 reads 16B aligned
    __shared__ float Bs[32][64];   // [k][n]

    int tid = threadIdx.x;
    int tx = tid & 15;
    int ty = tid >> 4;

    float acc[4][4] = {};

    for (int k0 = 0; k0 < KDIM; k0 += 32) {
#pragma unroll
        for (int i = 0; i < 8; i++) {
            int e = tid + i * 256;
            int k = e & 31;
            int m = e >> 5;
            int row = bm + m;
            As[k][m] = (row < M) ? A[row * KDIM + k0 + k] : 0.f;
        }
#pragma unroll
        for (int i = 0; i < 8; i++) {
            int e = tid + i * 256;
            int n = e & 63;
            int k = e >> 6;
            Bs[k][n] = B[(k0 + k) * Nc + bn + n];
        }
        __syncthreads();
#pragma unroll
        for (int k = 0; k < 32; k++) {
            float4 a = *(const float4*)&As[k][ty * 4];
            float4 b = *(const float4*)&Bs[k][tx * 4];
            float av[4] = {a.x, a.y, a.z, a.w};
            float bv[4] = {b.x, b.y, b.z, b.w};
#pragma unroll
            for (int i = 0; i < 4; i++)
#pragma unroll
                for (int j = 0; j < 4; j++)
                    acc[i][j] += av[i] * bv[j];
        }
        __syncthreads();
    }
#pragma unroll
    for (int i = 0; i < 4; i++) {
        int row = bm + ty * 4 + i;
        if (row < M) {
            float4 r = make_float4(acc[i][0], acc[i][1], acc[i][2], acc[i][3]);
            *(float4*)&C[row * Nc + bn + tx * 4] = r;
            __half2 p0 = __floats2half2_rn(acc[i][0], acc[i][1]);
            __half2 p1 = __floats2half2_rn(acc[i][2], acc[i][3]);
            uint2 hp;
            hp.x = *(unsigned*)&p0;
            hp.y = *(unsigned*)&p1;
            *(uint2*)&Ch[row * Nc + bn + tx * 4] = hp;
        }
    }
}

// ---------------- fused layer-0 GEMM + edge-bucket scatter ----------------
// Blocks [0, GEMM0_BLOCKS): z = feat @ W0 (independent of scatter).
// Blocks [GEMM0_BLOCKS, FUSED_BLOCKS): bucketed scatter (atomic-latency-bound,
// hides behind GEMM compute on the same SMs).
__global__ void fused_l0_kernel(const float* __restrict__ A, const float* __restrict__ B,
                                float* __restrict__ C, __half* __restrict__ Ch,
                                const int* __restrict__ src, const int* __restrict__ dst) {
    int b = blockIdx.x;
    if (b < GEMM0_BLOCKS) {
        gemm_body(A, B, C, Ch, NN, 128, (b >> 1) * 64, (b & 1) * 64);
    } else {
        int t = (b - GEMM0_BLOCKS) * blockDim.x + threadIdx.x;  // one thread = 4 edges
        int4 dv = ((const int4*)dst)[t];
        int4 sv = ((const int4*)src)[t];
        int p0 = atomicAdd(&g_cnt[dv.x], 1);
        int p1 = atomicAdd(&g_cnt[dv.y], 1);
        int p2 = atomicAdd(&g_cnt[dv.z], 1);
        int p3 = atomicAdd(&g_cnt[dv.w], 1);
        g_eb[dv.x * CAP + p0] = sv.x;
        g_eb[dv.y * CAP + p1] = sv.y;
        g_eb[dv.z * CAP + p2] = sv.z;
        g_eb[dv.w * CAP + p3] = sv.w;
    }
}

__global__ void gemm64_kernel(const float* __restrict__ A, const float* __restrict__ B,
                              float* __restrict__ C, __half* __restrict__ Ch,
                              int M, int Nc) {
    gemm_body(A, B, C, Ch, M, Nc, blockIdx.x * 64, blockIdx.y * 64);
}

// ---------------- aggregation: out[v] = z[v] + sum_{u in bucket v} z[u] ----------------
// 128 cols: warp per row, lane owns 4 cols (8B fp16 loads).
// 8-edge unroll; two 4-edge HADD2 trees feed two independent fp32 accumulators.
__global__ void agg128_kernel(const float* __restrict__ z, const __half* __restrict__ zh,
                              float* __restrict__ out) {
    int gw = (blockIdx.x * blockDim.x + threadIdx.x) >> 5;
    if (gw >= NN) return;
    int lane = threadIdx.x & 31;
    const float4* z4 = (const float4*)z;
    const uint2* zh2 = (const uint2*)zh;

    float4 self = z4[gw * 32 + lane];
    float4 aA = make_float4(0, 0, 0, 0);
    float4 aB = make_float4(0, 0, 0, 0);

    int n = g_cnt[gw];
    int s = gw * CAP;
    int j = 0;
    for (; j + 8 <= n; j += 8) {
        int4 i0 = *(const int4*)&g_eb[s + j];
        int4 i1 = *(const int4*)&g_eb[s + j + 4];
        uint2 v0 = zh2[i0.x * 32 + lane];
        uint2 v1 = zh2[i0.y * 32 + lane];
        uint2 v2 = zh2[i0.z * 32 + lane];
        uint2 v3 = zh2[i0.w * 32 + lane];
        uint2 v4 = zh2[i1.x * 32 + lane];
        uint2 v5 = zh2[i1.y * 32 + lane];
        uint2 v6 = zh2[i1.z * 32 + lane];
        uint2 v7 = zh2[i1.w * 32 + lane];
        // group A = v0+v1+v2+v3 (pairwise fp16 tree), group B = v4..v7
        __half2 gAx = __hadd2(__hadd2(u2h(v0.x), u2h(v1.x)), __hadd2(u2h(v2.x), u2h(v3.x)));
        __half2 gAy = __hadd2(__hadd2(u2h(v0.y), u2h(v1.y)), __hadd2(u2h(v2.y), u2h(v3.y)));
        __half2 gBx = __hadd2(__hadd2(u2h(v4.x), u2h(v5.x)), __hadd2(u2h(v6.x), u2h(v7.x)));
        __half2 gBy = __hadd2(__hadd2(u2h(v4.y), u2h(v5.y)), __hadd2(u2h(v6.y), u2h(v7.y)));
        float2 fa0 = __half22float2(gAx);
        float2 fa1 = __half22float2(gAy);
        float2 fb0 = __half22float2(gBx);
        float2 fb1 = __half22float2(gBy);
        aA.x += fa0.x; aA.y += fa0.y; aA.z += fa1.x; aA.w += fa1.y;
        aB.x += fb0.x; aB.y += fb0.y; aB.z += fb1.x; aB.w += fb1.y;
    }
    for (; j < n; j++) {
        uint2 v = zh2[g_eb[s + j] * 32 + lane];
        float2 f0 = __half22float2(u2h(v.x));
        float2 f1 = __half22float2(u2h(v.y));
        aA.x += f0.x; aA.y += f0.y; aA.z += f1.x; aA.w += f1.y;
    }
    float4 r;
    r.x = self.x + aA.x + aB.x;
    r.y = self.y + aA.y + aB.y;
    r.z = self.z + aA.z + aB.z;
    r.w = self.w + aA.w + aB.w;
    ((float4*)out)[gw * 32 + lane] = r;
}

// 64 cols: lane owns 2 cols (4B fp16 loads), same 8-edge / two-tree structure
__global__ void agg64_kernel(const float* __restrict__ z, const __half* __restrict__ zh,
                             float* __restrict__ out) {
    int gw = (blockIdx.x * blockDim.x + threadIdx.x) >> 5;
    if (gw >= NN) return;
    int lane = threadIdx.x & 31;
    const float2* z2 = (const float2*)z;
    const unsigned* zhu = (const unsigned*)zh;   // NN*64 halves = NN*32 uints

    float2 self = z2[gw * 32 + lane];
    float2 aA = make_float2(0, 0);
    float2 aB = make_float2(0, 0);

    int n = g_cnt[gw];
    int s = gw * CAP;
    int j = 0;
    for (; j + 8 <= n; j += 8) {
        int4 i0 = *(const int4*)&g_eb[s + j];
        int4 i1 = *(const int4*)&g_eb[s + j + 4];
        unsigned v0 = zhu[i0.x * 32 + lane];
        unsigned v1 = zhu[i0.y * 32 + lane];
        unsigned v2 = zhu[i0.z * 32 + lane];
        unsigned v3 = zhu[i0.w * 32 + lane];
        unsigned v4 = zhu[i1.x * 32 + lane];
        unsigned v5 = zhu[i1.y * 32 + lane];
        unsigned v6 = zhu[i1.z * 32 + lane];
        unsigned v7 = zhu[i1.w * 32 + lane];
        __half2 gA = __hadd2(__hadd2(u2h(v0), u2h(v1)), __hadd2(u2h(v2), u2h(v3)));
        __half2 gB = __hadd2(__hadd2(u2h(v4), u2h(v5)), __hadd2(u2h(v6), u2h(v7)));
        float2 fa = __half22float2(gA);
        float2 fb = __half22float2(gB);
        aA.x += fa.x; aA.y += fa.y;
        aB.x += fb.x; aB.y += fb.y;
    }
    for (; j < n; j++) {
        float2 f = __half22float2(u2h(zhu[g_eb[s + j] * 32 + lane]));
        aA.x += f.x; aA.y += f.y;
    }
    float2 r;
    r.x = self.x + aA.x + aB.x;
    r.y = self.y + aA.y + aB.y;
    ((float2*)out)[gw * 32 + lane] = r;
}

// ---------------- launch ----------------
extern "C" void kernel_launch(void* const* d_in, const int* in_sizes, int n_in,
                              void* d_out, int out_size) {
    const float* feat = (const float*)d_in[0];
    const float* W0   = (const float*)d_in[1];
    const float* W1   = (const float*)d_in[2];
    const float* W2   = (const float*)d_in[3];
    const int*   src  = (const int*)d_in[4];
    const int*   dst  = (const int*)d_in[5];
    float*       out  = (float*)d_out;

    void *pz, *ph, *pzh;
    cudaGetSymbolAddress(&pz, g_z);
    cudaGetSymbolAddress(&ph, g_h);
    cudaGetSymbolAddress(&pzh, g_zh);
    float*  z  = (float*)pz;
    float*  h  = (float*)ph;
    __half* zh = (__half*)pzh;

    const int AGG_BLOCKS = (NN * 32 + 255) / 256;

    // zero counters, then fused {layer-0 GEMM || bucket scatter}
    zero_cnt_kernel<<<(NN + 255) / 256, 256>>>();
    fused_l0_kernel<<<FUSED_BLOCKS, 256>>>(feat, W0, z, zh, src, dst);
    agg128_kernel<<<AGG_BLOCKS, 256>>>(z, zh, h);
    // layer 1
    gemm64_kernel<<<dim3(157, 2), 256>>>(h, W1, z, zh, NN, 128);
    agg128_kernel<<<AGG_BLOCKS, 256>>>(z, zh, h);
    // layer 2 (64 cols)
    gemm64_kernel<<<dim3(157, 1), 256>>>(h, W2, z, zh, NN, 64);
    agg64_kernel<<<AGG_BLOCKS, 256>>>(z, zh, out);
}

// round 9
// speedup vs baseline: 1.8894x; 1.1576x over previous
#include <cuda_runtime.h>
#include <cuda_fp16.h>

#define NN   10000
#define EE   640000
#define KDIM 128
#define CAP  160

// gemm tiling: (10000+63)/64 = 157 row-blocks
#define GEMM0_BLOCKS 314            // 157 x 2 col-blocks of 64 over Nc=128
#define SCAT_BLOCKS  625            // 625*256*4 = 640000 edges
#define FUSED_BLOCKS (GEMM0_BLOCKS + SCAT_BLOCKS)
#define AGG_BLOCKS   1250           // 10000 warps

// prep kernel block ranges
#define PREP_FEAT   1250            // 10000*128 f32 = 320000 float4
#define PREP_W0     (PREP_FEAT + 16)
#define PREP_W1     (PREP_W0 + 16)
#define PREP_W2     (PREP_W1 + 8)
#define PREP_TOTAL  (PREP_W2 + 10)  // + counter zeroing

// smem row strides (halves); multiples of 8 (16B) and conflict-free for LDSM
#define APAD 136
#define BPAD 72

// ---------------- scratch (device globals, no allocation) ----------------
__device__ int    g_cnt[NN];
__device__ int    g_eb[NN * CAP];           // padded per-node src buckets
__device__ float  g_z[NN * KDIM];           // fp32 z (self term for agg)
__device__ __half g_zh[NN * KDIM];          // fp16 z (gather operand)
__device__ __half g_h16[NN * KDIM];         // fp16 h (next-layer GEMM A)
__device__ __half g_feat16[NN * KDIM];
__device__ __half g_w0h[KDIM * KDIM];
__device__ __half g_w1h[KDIM * KDIM];
__device__ __half g_w2h[KDIM * 64];

__device__ __forceinline__ __half2 u2h(unsigned u) { return *reinterpret_cast<__half2*>(&u); }

__device__ __forceinline__ uint2 f4_to_h4(float4 v) {
    __half2 h0 = __floats2half2_rn(v.x, v.y);
    __half2 h1 = __floats2half2_rn(v.z, v.w);
    uint2 r;
    r.x = *(unsigned*)&h0;
    r.y = *(unsigned*)&h1;
    return r;
}

// ---------------- prep: fp16 conversions + counter zeroing ----------------
__global__ void prep_kernel(const float* __restrict__ feat, const float* __restrict__ W0,
                            const float* __restrict__ W1, const float* __restrict__ W2) {
    int b = blockIdx.x, t = threadIdx.x;
    if (b < PREP_FEAT) {
        int i = b * 256 + t;
        ((uint2*)g_feat16)[i] = f4_to_h4(((const float4*)feat)[i]);
    } else if (b < PREP_W0) {
        int i = (b - PREP_FEAT) * 256 + t;
        ((uint2*)g_w0h)[i] = f4_to_h4(((const float4*)W0)[i]);
    } else if (b < PREP_W1) {
        int i = (b - PREP_W0) * 256 + t;
        ((uint2*)g_w1h)[i] = f4_to_h4(((const float4*)W1)[i]);
    } else if (b < PREP_W2) {
        int i = (b - PREP_W1) * 256 + t;
        ((uint2*)g_w2h)[i] = f4_to_h4(((const float4*)W2)[i]);
    } else {
        int i = (b - PREP_W2) * 256 + t;          // 2560 threads cover 2500 int4
        if (i < NN / 4) ((int4*)g_cnt)[i] = make_int4(0, 0, 0, 0);
    }
}

// ---------------- tensor-core GEMM: C[M,Nc] = A16[M,128] @ B16[128,Nc] ----------------
__device__ __forceinline__ unsigned smem_u32(const void* p) {
    return (unsigned)__cvta_generic_to_shared(p);
}
__device__ __forceinline__ void ldsm_x4(unsigned& r0, unsigned& r1, unsigned& r2, unsigned& r3,
                                        unsigned addr) {
    asm volatile("ldmatrix.sync.aligned.m8n8.x4.shared.b16 {%0,%1,%2,%3}, [%4];"
                 : "=r"(r0), "=r"(r1), "=r"(r2), "=r"(r3) : "r"(addr));
}
__device__ __forceinline__ void ldsm_x4_t(unsigned& r0, unsigned& r1, unsigned& r2, unsigned& r3,
                                          unsigned addr) {
    asm volatile("ldmatrix.sync.aligned.m8n8.x4.trans.shared.b16 {%0,%1,%2,%3}, [%4];"
                 : "=r"(r0), "=r"(r1), "=r"(r2), "=r"(r3) : "r"(addr));
}
__device__ __forceinline__ void mma_16816(float* c, unsigned a0, unsigned a1, unsigned a2,
                                          unsigned a3, unsigned b0, unsigned b1) {
    asm volatile(
        "mma.sync.aligned.m16n8k16.row.col.f32.f16.f16.f32 "
        "{%0,%1,%2,%3}, {%4,%5,%6,%7}, {%8,%9}, {%0,%1,%2,%3};"
        : "+f"(c[0]), "+f"(c[1]), "+f"(c[2]), "+f"(c[3])
        : "r"(a0), "r"(a1), "r"(a2), "r"(a3), "r"(b0), "r"(b1));
}

// 64x64 tile, 8 warps (warp: 16 rows x 32 cols), whole K=128 staged once.
__device__ __forceinline__ void gemm_mma_body(const __half* __restrict__ A16,
                                              const __half* __restrict__ B16,
                                              float* __restrict__ C, __half* __restrict__ Ch,
                                              int M, int Nc, int bm, int bn) {
    __shared__ __half As[64 * APAD];
    __shared__ __half Bs[128 * BPAD];
    int tid = threadIdx.x;

    // A: 64 rows x 128 halves = 1024 uint4 (8 halves each), 16 uint4/row
#pragma unroll
    for (int i = 0; i < 4; i++) {
        int idx = tid + i * 256;
        int row = idx >> 4;
        int c8 = idx & 15;
        int grow = bm + row;
        uint4 v = make_uint4(0, 0, 0, 0);
        if (grow < M) v = *(const uint4*)(A16 + (size_t)grow * KDIM + c8 * 8);
        *(uint4*)(As + row * APAD + c8 * 8) = v;
    }
    // B: 128 rows x 64 halves = 8 uint4/row = 1024 uint4
#pragma unroll
    for (int i = 0; i < 4; i++) {
        int idx = tid + i * 256;
        int row = idx >> 3;
        int c8 = idx & 7;
        uint4 v = *(const uint4*)(B16 + (size_t)row * Nc + bn + c8 * 8);
        *(uint4*)(Bs + row * BPAD + c8 * 8) = v;
    }
    __syncthreads();

    int wid = tid >> 5, lane = tid & 31;
    int wm = (wid & 3) * 16;    // warp row offset in tile
    int wn = (wid >> 2) * 32;   // warp col offset in tile
    float c[4][4] = {};         // 4 n8-tiles x 4 accum regs

    int jhi = lane >> 3;        // ldmatrix source-row group
#pragma unroll
    for (int ks = 0; ks < 8; ks++) {
        unsigned a0, a1, a2, a3;
        // A frag m16k16: lanes 0-15 rows wm+0..15 @k+0, lanes 16-31 same rows @k+8
        ldsm_x4(a0, a1, a2, a3,
                smem_u32(As + (wm + (lane & 15)) * APAD + (lane >> 4) * 8 + ks * 16));
#pragma unroll
        for (int nh = 0; nh < 2; nh++) {
            // B frag k16 x n16 (trans): j0=(k0,n0) j1=(k8,n0) j2=(k0,n8) j3=(k8,n8)
            int krow = ks * 16 + (jhi & 1) * 8 + (lane & 7);
            int ncol = wn + nh * 16 + (jhi >> 1) * 8;
            unsigned b0, b1, b2, b3;
            ldsm_x4_t(b0, b1, b2, b3, smem_u32(Bs + krow * BPAD + ncol));
            mma_16816(c[2 * nh + 0], a0, a1, a2, a3, b0, b1);
            mma_16816(c[2 * nh + 1], a0, a1, a2, a3, b2, b3);
        }
    }

    // epilogue: c[t] covers rows (wm + lane/4, +8), cols wn + t*8 + (lane%4)*2
    int r0 = bm + wm + (lane >> 2);
    int col0 = bn + wn + (lane & 3) * 2;
#pragma unroll
    for (int t = 0; t < 4; t++) {
        int col = col0 + t * 8;
        if (r0 < M) {
            *(float2*)(C + (size_t)r0 * Nc + col) = make_float2(c[t][0], c[t][1]);
            *(__half2*)(Ch + (size_t)r0 * Nc + col) = __floats2half2_rn(c[t][0], c[t][1]);
        }
        int r1 = r0 + 8;
        if (r1 < M) {
            *(float2*)(C + (size_t)r1 * Nc + col) = make_float2(c[t][2], c[t][3]);
            *(__half2*)(Ch + (size_t)r1 * Nc + col) = __floats2half2_rn(c[t][2], c[t][3]);
        }
    }
}

// ---------------- fused layer-0 GEMM + edge-bucket scatter ----------------
__global__ void fused_l0_kernel(const int* __restrict__ src, const int* __restrict__ dst) {
    int b = blockIdx.x;
    if (b < GEMM0_BLOCKS) {
        gemm_mma_body(g_feat16, g_w0h, g_z, g_zh, NN, 128, (b >> 1) * 64, (b & 1) * 64);
    } else {
        int t = (b - GEMM0_BLOCKS) * blockDim.x + threadIdx.x;  // one thread = 4 edges
        int4 dv = ((const int4*)dst)[t];
        int4 sv = ((const int4*)src)[t];
        int p0 = atomicAdd(&g_cnt[dv.x], 1);
        int p1 = atomicAdd(&g_cnt[dv.y], 1);
        int p2 = atomicAdd(&g_cnt[dv.z], 1);
        int p3 = atomicAdd(&g_cnt[dv.w], 1);
        g_eb[dv.x * CAP + p0] = sv.x;
        g_eb[dv.y * CAP + p1] = sv.y;
        g_eb[dv.z * CAP + p2] = sv.z;
        g_eb[dv.w * CAP + p3] = sv.w;
    }
}

__global__ void gemm_mma_kernel(const __half* __restrict__ A16, const __half* __restrict__ B16,
                                float* __restrict__ C, __half* __restrict__ Ch, int M, int Nc) {
    gemm_mma_body(A16, B16, C, Ch, M, Nc, blockIdx.x * 64, blockIdx.y * 64);
}

// ---------------- aggregation: h[v] = z[v] + sum_{u in bucket v} z[u] ----------------
// 128 cols: warp per row, lane owns 4 cols; 8-edge unroll, two HADD2 trees.
// Output: fp16 only (next GEMM consumes fp16).
__global__ void agg128_kernel(const float* __restrict__ z, const __half* __restrict__ zh,
                              __half* __restrict__ outh) {
    int gw = (blockIdx.x * blockDim.x + threadIdx.x) >> 5;
    if (gw >= NN) return;
    int lane = threadIdx.x & 31;
    const float4* z4 = (const float4*)z;
    const uint2* zh2 = (const uint2*)zh;

    float4 self = z4[gw * 32 + lane];
    float4 aA = make_float4(0, 0, 0, 0);
    float4 aB = make_float4(0, 0, 0, 0);

    int n = g_cnt[gw];
    int s = gw * CAP;
    int j = 0;
    for (; j + 8 <= n; j += 8) {
        int4 i0 = *(const int4*)&g_eb[s + j];
        int4 i1 = *(const int4*)&g_eb[s + j + 4];
        uint2 v0 = zh2[i0.x * 32 + lane];
        uint2 v1 = zh2[i0.y * 32 + lane];
        uint2 v2 = zh2[i0.z * 32 + lane];
        uint2 v3 = zh2[i0.w * 32 + lane];
        uint2 v4 = zh2[i1.x * 32 + lane];
        uint2 v5 = zh2[i1.y * 32 + lane];
        uint2 v6 = zh2[i1.z * 32 + lane];
        uint2 v7 = zh2[i1.w * 32 + lane];
        __half2 gAx = __hadd2(__hadd2(u2h(v0.x), u2h(v1.x)), __hadd2(u2h(v2.x), u2h(v3.x)));
        __half2 gAy = __hadd2(__hadd2(u2h(v0.y), u2h(v1.y)), __hadd2(u2h(v2.y), u2h(v3.y)));
        __half2 gBx = __hadd2(__hadd2(u2h(v4.x), u2h(v5.x)), __hadd2(u2h(v6.x), u2h(v7.x)));
        __half2 gBy = __hadd2(__hadd2(u2h(v4.y), u2h(v5.y)), __hadd2(u2h(v6.y), u2h(v7.y)));
        float2 fa0 = __half22float2(gAx);
        float2 fa1 = __half22float2(gAy);
        float2 fb0 = __half22float2(gBx);
        float2 fb1 = __half22float2(gBy);
        aA.x += fa0.x; aA.y += fa0.y; aA.z += fa1.x; aA.w += fa1.y;
        aB.x += fb0.x; aB.y += fb0.y; aB.z += fb1.x; aB.w += fb1.y;
    }
    for (; j < n; j++) {
        uint2 v = zh2[g_eb[s + j] * 32 + lane];
        float2 f0 = __half22float2(u2h(v.x));
        float2 f1 = __half22float2(u2h(v.y));
        aA.x += f0.x; aA.y += f0.y; aA.z += f1.x; aA.w += f1.y;
    }
    float4 r;
    r.x = self.x + aA.x + aB.x;
    r.y = self.y + aA.y + aB.y;
    r.z = self.z + aA.z + aB.z;
    r.w = self.w + aA.w + aB.w;
    uint2 hp;
    hp.x = *(unsigned*)&(__half2&)*(__half2[]){__floats2half2_rn(r.x, r.y)};
    hp.y = *(unsigned*)&(__half2&)*(__half2[]){__floats2half2_rn(r.z, r.w)};
    ((uint2*)outh)[gw * 32 + lane] = hp;
}

// 64 cols (last layer): lane owns 2 cols; fp32 output to d_out.
__global__ void agg64_kernel(const float* __restrict__ z, const __half* __restrict__ zh,
                             float* __restrict__ out) {
    int gw = (blockIdx.x * blockDim.x + threadIdx.x) >> 5;
    if (gw >= NN) return;
    int lane = threadIdx.x & 31;
    const float2* z2 = (const float2*)z;
    const unsigned* zhu = (const unsigned*)zh;

    float2 self = z2[gw * 32 + lane];
    float2 aA = make_float2(0, 0);
    float2 aB = make_float2(0, 0);

    int n = g_cnt[gw];
    int s = gw * CAP;
    int j = 0;
    for (; j + 8 <= n; j += 8) {
        int4 i0 = *(const int4*)&g_eb[s + j];
        int4 i1 = *(const int4*)&g_eb[s + j + 4];
        unsigned v0 = zhu[i0.x * 32 + lane];
        unsigned v1 = zhu[i0.y * 32 + lane];
        unsigned v2 = zhu[i0.z * 32 + lane];
        unsigned v3 = zhu[i0.w * 32 + lane];
        unsigned v4 = zhu[i1.x * 32 + lane];
        unsigned v5 = zhu[i1.y * 32 + lane];
        unsigned v6 = zhu[i1.z * 32 + lane];
        unsigned v7 = zhu[i1.w * 32 + lane];
        __half2 gA = __hadd2(__hadd2(u2h(v0), u2h(v1)), __hadd2(u2h(v2), u2h(v3)));
        __half2 gB = __hadd2(__hadd2(u2h(v4), u2h(v5)), __hadd2(u2h(v6), u2h(v7)));
        float2 fa = __half22float2(gA);
        float2 fb = __half22float2(gB);
        aA.x += fa.x; aA.y += fa.y;
        aB.x += fb.x; aB.y += fb.y;
    }
    for (; j < n; j++) {
        float2 f = __half22float2(u2h(zhu[g_eb[s + j] * 32 + lane]));
        aA.x += f.x; aA.y += f.y;
    }
    float2 r;
    r.x = self.x + aA.x + aB.x;
    r.y = self.y + aA.y + aB.y;
    ((float2*)out)[gw * 32 + lane] = r;
}

// ---------------- launch ----------------
extern "C" void kernel_launch(void* const* d_in, const int* in_sizes, int n_in,
                              void* d_out, int out_size) {
    const float* feat = (const float*)d_in[0];
    const float* W0   = (const float*)d_in[1];
    const float* W1   = (const float*)d_in[2];
    const float* W2   = (const float*)d_in[3];
    const int*   src  = (const int*)d_in[4];
    const int*   dst  = (const int*)d_in[5];
    float*       out  = (float*)d_out;

    void *pz, *pzh, *ph16, *pw1, *pw2;
    cudaGetSymbolAddress(&pz, g_z);
    cudaGetSymbolAddress(&pzh, g_zh);
    cudaGetSymbolAddress(&ph16, g_h16);
    cudaGetSymbolAddress(&pw1, g_w1h);
    cudaGetSymbolAddress(&pw2, g_w2h);
    float*  z   = (float*)pz;
    __half* zh  = (__half*)pzh;
    __half* h16 = (__half*)ph16;
    __half* w1h = (__half*)pw1;
    __half* w2h = (__half*)pw2;

    // prep: fp16 conversions + counter zeroing
    prep_kernel<<<PREP_TOTAL, 256>>>(feat, W0, W1, W2);
    // fused: layer-0 GEMM (tensor cores) || bucket scatter
    fused_l0_kernel<<<FUSED_BLOCKS, 256>>>(src, dst);
    agg128_kernel<<<AGG_BLOCKS, 256>>>(z, zh, h16);
    // layer 1
    gemm_mma_kernel<<<dim3(157, 2), 256>>>(h16, w1h, z, zh, NN, 128);
    agg128_kernel<<<AGG_BLOCKS, 256>>>(z, zh, h16);
    // layer 2 (64 cols)
    gemm_mma_kernel<<<dim3(157, 1), 256>>>(h16, w2h, z, zh, NN, 64);
    agg64_kernel<<<AGG_BLOCKS, 256>>>(z, zh, out);
}